// round 15
// baseline (speedup 1.0000x reference)
#include <cuda_runtime.h>
#include <cstdint>

#define BATCH   64
#define NBLK    (BATCH * 2)     // 2-CTA cluster per image
#define TPB     544             // 17 warps: 16 compute + 1 controller
#define NPATCH  (127 * 127)

__device__ __forceinline__ uint32_t smem_u32(const void* p) {
    uint32_t a;
    asm("{ .reg .u64 t; cvta.to.shared.u64 t, %1; cvt.u32.u64 %0, t; }"
        : "=r"(a) : "l"(p));
    return a;
}

__global__ void __launch_bounds__(TPB, 1) __cluster_dims__(2, 1, 1)
fused_kernel(
    const float* __restrict__ x,
    const float* __restrict__ conv_w,
    const float* __restrict__ conv_b,
    const float* __restrict__ ry,      // (2,4)
    const float* __restrict__ head_w,  // (1,2)
    const float* __restrict__ head_b,
    float* __restrict__ out)
{
    __shared__ float sm[512][9];    // [compute-thread][monomial], pad=9 (coprime 32)
    __shared__ float tot[8];        // this CTA's 8 monomial sums
    __shared__ float peer[8];       // CTA0: filled remotely by CTA1
    __shared__ __align__(8) unsigned long long mbar;

    const int tid  = threadIdx.x;
    const int wid  = tid >> 5;
    const int lane = tid & 31;
    const int b    = blockIdx.x >> 1;
    uint32_t rank;
    asm("mov.u32 %0, %%cluster_ctarank;" : "=r"(rank));

    const uint32_t mbar_a = smem_u32(&mbar);
    const uint32_t peer_a = smem_u32(peer);

    // ---- front-batched pixel loads FIRST: start the DRAM wall ASAP ----
    const int rowbase = (int)rank * 64 + wid * 4;
    float4 v[4];
    if (wid < 16) {
        const float* __restrict__ p =
            x + (size_t)b * 16384 + rowbase * 128 + lane * 4;
        #pragma unroll
        for (int i = 0; i < 4; i++) v[i] = *(const float4*)(p + i * 128);
    }

    // mbarrier init (CTA0 only); ordered before remote arrive by the split
    // cluster barrier below.
    if (rank == 0 && tid == 0) {
        asm volatile("mbarrier.init.shared.b64 [%0], 1;" :: "r"(mbar_a) : "memory");
    }
    __syncthreads();
    asm volatile("barrier.cluster.arrive.aligned;" ::: "memory");

    // ---- controller (warp 16 lane 0, rank 0): coefficient chain,
    //      overlapped with the DRAM load wall + main phase ----
    float Ac = 0.f, Bc = 0.f, Cc = 0.f, Dc = 0.f, Ec = 0.f;
    float cw0 = 0.f, cw1 = 0.f, cw2 = 0.f, cw3 = 0.f, cK = 0.f;
    if (rank == 0 && wid == 16 && lane == 0) {
        float pr[8];
        #pragma unroll
        for (int i = 0; i < 8; i++) pr[i] = ry[i];
        const float ph0 = head_w[0], ph1 = head_w[1];

        float U[4][4] = {{1,0,0,0},{0,1,0,0},{0,0,1,0},{0,0,0,1}};
        #pragma unroll
        for (int l = 0; l < 2; l++) {
            float c0, s0, c1, s1;
            __sincosf(0.5f * pr[l * 4 + 0], &s0, &c0);
            __sincosf(0.5f * pr[l * 4 + 1], &s1, &c1);
            float A2[2][2] = {{c0, -s0}, {s0, c0}};
            float B2[2][2] = {{c1, -s1}, {s1, c1}};
            float T4[4][4];
            #pragma unroll
            for (int i = 0; i < 4; i++)
                #pragma unroll
                for (int j = 0; j < 4; j++) {
                    float s = 0.f;
                    #pragma unroll
                    for (int kx = 0; kx < 4; kx++)
                        s += A2[i >> 1][kx >> 1] * B2[i & 1][kx & 1] * U[kx][j];
                    T4[i][j] = s;
                }
            #pragma unroll
            for (int j = 0; j < 4; j++) {
                U[0][j] = T4[0][j]; U[1][j] = T4[1][j];
                U[2][j] = T4[3][j]; U[3][j] = T4[2][j];
            }
        }
        float M00 = 0, M03 = 0, M33 = 0, M11 = 0, M12 = 0, M22 = 0;
        #pragma unroll
        for (int i = 0; i < 4; i++) {
            float z = (i < 2) ? 1.0f : -1.0f;
            M00 += z * U[i][0] * U[i][0];
            M03 += z * U[i][0] * U[i][3];
            M33 += z * U[i][3] * U[i][3];
            M11 += z * U[i][1] * U[i][1];
            M12 += z * U[i][1] * U[i][2];
            M22 += z * U[i][2] * U[i][2];
        }
        const float c_q0 = ph1 * M00;
        const float c_q1 = ph1 * (-2.0f * M03);
        const float c_q2 = ph1 * M33;
        const float c_q3 = ph1 * M11;
        const float c_q4 = ph1 * (2.0f * M12);
        const float c_q5 = ph1 * M22;
        Ac = 0.25f * (c_q0 + c_q2 + c_q3 + c_q5);
        Bc = 0.25f * (c_q0 - c_q2 + c_q3 - c_q5);
        Cc = 0.25f * (c_q0 - c_q2 - c_q3 + c_q5);
        Dc = 0.25f * (c_q0 + c_q2 - c_q3 - c_q5);
        Ec = 0.25f * (c_q1 + c_q4);
        cw0 = ph0 * conv_w[0]; cw1 = ph0 * conv_w[1];
        cw2 = ph0 * conv_w[2]; cw3 = ph0 * conv_w[3];
        cK  = ph0 * conv_b[0] + head_b[0];
    }

    // complete cluster barrier (hides under the load wall)
    asm volatile("barrier.cluster.wait.aligned;" ::: "memory");

    // ---- main phase (compute warps) ----
    if (wid < 16) {
        float S0 = 0.f, S1 = 0.f, S2 = 0.f, S3 = 0.f;
        float S4 = 0.f, S5 = 0.f, S6 = 0.f, S7 = 0.f;
        const bool l31 = (lane == 31);
        const bool l0  = (lane == 0);
        #pragma unroll
        for (int i = 0; i < 4; i++) {
            const int   row = rowbase + i;     // warp-uniform
            const float4 vv = v[i];
            const float rs = (vv.x + vv.y) + (vv.z + vv.w);
            const float e0 = l0  ? vv.x : 0.f;
            const float e3 = l31 ? vv.w : 0.f;

            if (row < 127) {
                S4 += rs - e3;                 // La0
                S5 += rs - e0;                 // La1
                float ca0, sa0, ca1, sa1, ca2, sa2, ca3, sa3;
                __sincosf(vv.x, &sa0, &ca0);
                __sincosf(vv.y, &sa1, &ca1);
                __sincosf(vv.z, &sa2, &ca2);
                __sincosf(vv.w, &sa3, &ca3);
                const float ca4 = __shfl_down_sync(0xFFFFFFFFu, ca0, 1);
                const float sa4 = __shfl_down_sync(0xFFFFFFFFu, sa0, 1);
                const float tc = (ca0 + ca1) + (ca2 + ca3);
                S0 += tc - (l31 ? ca3 : 0.f);  // Sca0
                S1 += tc - (l0  ? ca0 : 0.f);  // Sca1
                S2 += ca0 * ca1 + ca1 * ca2 + ca2 * ca3 + (l31 ? 0.f : ca3 * ca4);
                S3 += sa0 * sa1 + sa1 * sa2 + sa2 * sa3 + (l31 ? 0.f : sa3 * sa4);
            }
            if (row > 0) {
                S6 += rs - e3;                 // La2
                S7 += rs - e0;                 // La3
            }
        }
        // direct smem stash — no shuffle tree
        sm[tid][0] = S0; sm[tid][1] = S1; sm[tid][2] = S2; sm[tid][3] = S3;
        sm[tid][4] = S4; sm[tid][5] = S5; sm[tid][6] = S6; sm[tid][7] = S7;
    }
    __syncthreads();

    // ---- reducer warps 0-7: warp w sums monomial w over 512 threads ----
    // lane l reads t = k*32 + l (9 coprime 32 -> conflict-free), fixed order.
    if (wid < 8) {
        float acc = 0.f;
        #pragma unroll
        for (int k = 0; k < 16; k++) acc += sm[k * 32 + lane][wid];
        acc += __shfl_down_sync(0xFFFFFFFFu, acc, 16);
        acc += __shfl_down_sync(0xFFFFFFFFu, acc, 8);
        acc += __shfl_down_sync(0xFFFFFFFFu, acc, 4);
        acc += __shfl_down_sync(0xFFFFFFFFu, acc, 2);
        acc += __shfl_down_sync(0xFFFFFFFFu, acc, 1);
        if (lane == 0) tot[wid] = acc;
    }
    __syncthreads();

    // ---- CTA1: ship 8 sums to CTA0 via DSMEM, then release-arrive ----
    if (rank == 1 && wid == 16 && lane == 0) {
        uint32_t rp, rm;
        asm("mapa.shared::cluster.u32 %0, %1, 0;" : "=r"(rp) : "r"(peer_a));
        asm("mapa.shared::cluster.u32 %0, %1, 0;" : "=r"(rm) : "r"(mbar_a));
        #pragma unroll
        for (int i = 0; i < 8; i++) {
            asm volatile("st.shared::cluster.f32 [%0], %1;"
                         :: "r"(rp + 4 * i), "f"(tot[i]) : "memory");
        }
        asm volatile(
            "mbarrier.arrive.release.cluster.shared::cluster.b64 _, [%0];"
            :: "r"(rm) : "memory");
    }

    // ---- CTA0 controller: wait, combine, store ----
    if (rank == 0 && wid == 16 && lane == 0) {
        asm volatile(
            "{\n\t"
            ".reg .pred p;\n\t"
            "W%=:\n\t"
            "mbarrier.try_wait.parity.acquire.cluster.shared::cta.b64 p, [%0], 0, 0x989680;\n\t"
            "@p bra D%=;\n\t"
            "bra W%=;\n\t"
            "D%=:\n\t"
            "}"
            :: "r"(mbar_a) : "memory");

        // fixed order: CTA0 (rows 0-63) + CTA1 (rows 64-127)
        const float m0 = tot[0] + peer[0];
        const float m1 = tot[1] + peer[1];
        const float m2 = tot[2] + peer[2];
        const float m3 = tot[3] + peer[3];
        const float m4 = tot[4] + peer[4];
        const float m5 = tot[5] + peer[5];
        const float m6 = tot[6] + peer[6];
        const float m7 = tot[7] + peer[7];

        const float qsum = Ac * (float)NPATCH + Bc * m0 + Cc * m1
                         + Dc * m2 + Ec * m3;
        const float csum = cw0 * m4 + cw1 * m5 + cw2 * m6 + cw3 * m7;
        out[b] = (qsum + csum) * (1.0f / (float)NPATCH) + cK;
    }
}

extern "C" void kernel_launch(void* const* d_in, const int* in_sizes, int n_in,
                              void* d_out, int out_size) {
    const float* x      = (const float*)d_in[0];
    const float* conv_w = (const float*)d_in[1];
    const float* conv_b = (const float*)d_in[2];
    const float* ry     = (const float*)d_in[3];
    const float* head_w = (const float*)d_in[4];
    const float* head_b = (const float*)d_in[5];
    float* out = (float*)d_out;

    fused_kernel<<<NBLK, TPB>>>(x, conv_w, conv_b, ry, head_w, head_b, out);
}

// round 17
// speedup vs baseline: 1.0048x; 1.0048x over previous
#include <cuda_runtime.h>
#include <cstdint>

#define BATCH   64
#define NBLK    (BATCH * 2)     // 2-CTA cluster per image
#define TPB     544             // 17 warps: 16 compute + 1 controller
#define NPATCH  (127 * 127)

__device__ __forceinline__ uint32_t smem_u32(const void* p) {
    uint32_t a;
    asm("{ .reg .u64 t; cvta.to.shared.u64 t, %1; cvt.u32.u64 %0, t; }"
        : "=r"(a) : "l"(p));
    return a;
}

__global__ void __launch_bounds__(TPB, 1) __cluster_dims__(2, 1, 1)
fused_kernel(
    const float* __restrict__ x,
    const float* __restrict__ conv_w,
    const float* __restrict__ conv_b,
    const float* __restrict__ ry,      // (2,4)
    const float* __restrict__ head_w,  // (1,2)
    const float* __restrict__ head_b,
    float* __restrict__ out)
{
    __shared__ float sm[512][9];    // [compute-thread][monomial], pad 9 (coprime 32)
    __shared__ float tot[8];        // this CTA's 8 monomial sums
    __shared__ float peer[8];       // CTA0: filled remotely by CTA1
    __shared__ __align__(8) unsigned long long mbar;

    const int tid  = threadIdx.x;
    const int wid  = tid >> 5;
    const int lane = tid & 31;
    const int b    = blockIdx.x >> 1;
    uint32_t rank;
    asm("mov.u32 %0, %%cluster_ctarank;" : "=r"(rank));

    const uint32_t mbar_a = smem_u32(&mbar);
    const uint32_t peer_a = smem_u32(peer);

    // ---- front-batched pixel loads FIRST: start the DRAM wall ASAP ----
    const int rowbase = (int)rank * 64 + wid * 4;
    float4 v[4];
    if (wid < 16) {
        const float* __restrict__ p =
            x + (size_t)b * 16384 + rowbase * 128 + lane * 4;
        #pragma unroll
        for (int i = 0; i < 4; i++) v[i] = *(const float4*)(p + i * 128);
    }

    // mbarrier init (CTA0 tid0). Ordering to CTA1's remote arrive: init ->
    // (program order, tid0) cluster.arrive -> cluster.wait (CTA1, pre-tail)
    // -> remote store/arrive. Intra-CTA visibility to the controller is
    // covered by the whole-block __syncthreads below.
    if (rank == 0 && tid == 0) {
        asm volatile("mbarrier.init.shared.b64 [%0], 1;" :: "r"(mbar_a) : "memory");
    }
    // split cluster barrier: arrive now, wait just before the tail
    asm volatile("barrier.cluster.arrive.aligned;" ::: "memory");

    // ---- controller (warp 16 lane 0, rank 0): coefficient chain,
    //      overlapped with the DRAM load wall + main phase ----
    float Ac = 0.f, Bc = 0.f, Cc = 0.f, Dc = 0.f, Ec = 0.f;
    float cw0 = 0.f, cw1 = 0.f, cw2 = 0.f, cw3 = 0.f, cK = 0.f;
    if (rank == 0 && wid == 16 && lane == 0) {
        float pr[8];
        #pragma unroll
        for (int i = 0; i < 8; i++) pr[i] = ry[i];
        const float ph0 = head_w[0], ph1 = head_w[1];

        float U[4][4] = {{1,0,0,0},{0,1,0,0},{0,0,1,0},{0,0,0,1}};
        #pragma unroll
        for (int l = 0; l < 2; l++) {
            float c0, s0, c1, s1;
            __sincosf(0.5f * pr[l * 4 + 0], &s0, &c0);
            __sincosf(0.5f * pr[l * 4 + 1], &s1, &c1);
            float A2[2][2] = {{c0, -s0}, {s0, c0}};
            float B2[2][2] = {{c1, -s1}, {s1, c1}};
            float T4[4][4];
            #pragma unroll
            for (int i = 0; i < 4; i++)
                #pragma unroll
                for (int j = 0; j < 4; j++) {
                    float s = 0.f;
                    #pragma unroll
                    for (int kx = 0; kx < 4; kx++)
                        s += A2[i >> 1][kx >> 1] * B2[i & 1][kx & 1] * U[kx][j];
                    T4[i][j] = s;
                }
            #pragma unroll
            for (int j = 0; j < 4; j++) {
                U[0][j] = T4[0][j]; U[1][j] = T4[1][j];
                U[2][j] = T4[3][j]; U[3][j] = T4[2][j];
            }
        }
        float M00 = 0, M03 = 0, M33 = 0, M11 = 0, M12 = 0, M22 = 0;
        #pragma unroll
        for (int i = 0; i < 4; i++) {
            float z = (i < 2) ? 1.0f : -1.0f;
            M00 += z * U[i][0] * U[i][0];
            M03 += z * U[i][0] * U[i][3];
            M33 += z * U[i][3] * U[i][3];
            M11 += z * U[i][1] * U[i][1];
            M12 += z * U[i][1] * U[i][2];
            M22 += z * U[i][2] * U[i][2];
        }
        const float c_q0 = ph1 * M00;
        const float c_q1 = ph1 * (-2.0f * M03);
        const float c_q2 = ph1 * M33;
        const float c_q3 = ph1 * M11;
        const float c_q4 = ph1 * (2.0f * M12);
        const float c_q5 = ph1 * M22;
        Ac = 0.25f * (c_q0 + c_q2 + c_q3 + c_q5);
        Bc = 0.25f * (c_q0 - c_q2 + c_q3 - c_q5);
        Cc = 0.25f * (c_q0 - c_q2 - c_q3 + c_q5);
        Dc = 0.25f * (c_q0 + c_q2 - c_q3 - c_q5);
        Ec = 0.25f * (c_q1 + c_q4);
        cw0 = ph0 * conv_w[0]; cw1 = ph0 * conv_w[1];
        cw2 = ph0 * conv_w[2]; cw3 = ph0 * conv_w[3];
        cK  = ph0 * conv_b[0] + head_b[0];
    }

    // ---- main phase (compute warps) — no cluster wait on this path ----
    if (wid < 16) {
        float S0 = 0.f, S1 = 0.f, S2 = 0.f, S3 = 0.f;
        float S4 = 0.f, S5 = 0.f, S6 = 0.f, S7 = 0.f;
        const bool l31 = (lane == 31);
        const bool l0  = (lane == 0);
        #pragma unroll
        for (int i = 0; i < 4; i++) {
            const int   row = rowbase + i;     // warp-uniform
            const float4 vv = v[i];
            const float rs = (vv.x + vv.y) + (vv.z + vv.w);
            const float e0 = l0  ? vv.x : 0.f;
            const float e3 = l31 ? vv.w : 0.f;

            if (row < 127) {
                S4 += rs - e3;                 // La0
                S5 += rs - e0;                 // La1
                float ca0, sa0, ca1, sa1, ca2, sa2, ca3, sa3;
                __sincosf(vv.x, &sa0, &ca0);
                __sincosf(vv.y, &sa1, &ca1);
                __sincosf(vv.z, &sa2, &ca2);
                __sincosf(vv.w, &sa3, &ca3);
                const float ca4 = __shfl_down_sync(0xFFFFFFFFu, ca0, 1);
                const float sa4 = __shfl_down_sync(0xFFFFFFFFu, sa0, 1);
                const float tc = (ca0 + ca1) + (ca2 + ca3);
                S0 += tc - (l31 ? ca3 : 0.f);  // Sca0
                S1 += tc - (l0  ? ca0 : 0.f);  // Sca1
                S2 += ca0 * ca1 + ca1 * ca2 + ca2 * ca3 + (l31 ? 0.f : ca3 * ca4);
                S3 += sa0 * sa1 + sa1 * sa2 + sa2 * sa3 + (l31 ? 0.f : sa3 * sa4);
            }
            if (row > 0) {
                S6 += rs - e3;                 // La2
                S7 += rs - e0;                 // La3
            }
        }
        // direct smem stash — no shuffle tree
        sm[tid][0] = S0; sm[tid][1] = S1; sm[tid][2] = S2; sm[tid][3] = S3;
        sm[tid][4] = S4; sm[tid][5] = S5; sm[tid][6] = S6; sm[tid][7] = S7;
    }
    __syncthreads();

    // ---- reducer warps 0-7: warp w sums monomial w over 512 threads ----
    if (wid < 8) {
        float acc = 0.f;
        #pragma unroll
        for (int k = 0; k < 16; k++) acc += sm[k * 32 + lane][wid];
        acc += __shfl_down_sync(0xFFFFFFFFu, acc, 16);
        acc += __shfl_down_sync(0xFFFFFFFFu, acc, 8);
        acc += __shfl_down_sync(0xFFFFFFFFu, acc, 4);
        acc += __shfl_down_sync(0xFFFFFFFFu, acc, 2);
        acc += __shfl_down_sync(0xFFFFFFFFu, acc, 1);
        if (lane == 0) tot[wid] = acc;
    }
    __syncthreads();

    // complete the cluster barrier only now — skew hidden under main phase
    asm volatile("barrier.cluster.wait.aligned;" ::: "memory");

    // ---- CTA1: ship 8 sums to CTA0 via DSMEM, then release-arrive ----
    if (rank == 1 && wid == 16 && lane == 0) {
        uint32_t rp, rm;
        asm("mapa.shared::cluster.u32 %0, %1, 0;" : "=r"(rp) : "r"(peer_a));
        asm("mapa.shared::cluster.u32 %0, %1, 0;" : "=r"(rm) : "r"(mbar_a));
        #pragma unroll
        for (int i = 0; i < 8; i++) {
            asm volatile("st.shared::cluster.f32 [%0], %1;"
                         :: "r"(rp + 4 * i), "f"(tot[i]) : "memory");
        }
        asm volatile(
            "mbarrier.arrive.release.cluster.shared::cluster.b64 _, [%0];"
            :: "r"(rm) : "memory");
    }

    // ---- CTA0 controller: wait, combine, store ----
    if (rank == 0 && wid == 16 && lane == 0) {
        asm volatile(
            "{\n\t"
            ".reg .pred p;\n\t"
            "W%=:\n\t"
            "mbarrier.try_wait.parity.acquire.cluster.shared::cta.b64 p, [%0], 0, 0x989680;\n\t"
            "@p bra D%=;\n\t"
            "bra W%=;\n\t"
            "D%=:\n\t"
            "}"
            :: "r"(mbar_a) : "memory");

        // fixed order: CTA0 (rows 0-63) + CTA1 (rows 64-127)
        const float m0 = tot[0] + peer[0];
        const float m1 = tot[1] + peer[1];
        const float m2 = tot[2] + peer[2];
        const float m3 = tot[3] + peer[3];
        const float m4 = tot[4] + peer[4];
        const float m5 = tot[5] + peer[5];
        const float m6 = tot[6] + peer[6];
        const float m7 = tot[7] + peer[7];

        const float qsum = Ac * (float)NPATCH + Bc * m0 + Cc * m1
                         + Dc * m2 + Ec * m3;
        const float csum = cw0 * m4 + cw1 * m5 + cw2 * m6 + cw3 * m7;
        out[b] = (qsum + csum) * (1.0f / (float)NPATCH) + cK;
    }
}

extern "C" void kernel_launch(void* const* d_in, const int* in_sizes, int n_in,
                              void* d_out, int out_size) {
    const float* x      = (const float*)d_in[0];
    const float* conv_w = (const float*)d_in[1];
    const float* conv_b = (const float*)d_in[2];
    const float* ry     = (const float*)d_in[3];
    const float* head_w = (const float*)d_in[4];
    const float* head_b = (const float*)d_in[5];
    float* out = (float*)d_out;

    fused_kernel<<<NBLK, TPB>>>(x, conv_w, conv_b, ry, head_w, head_b, out);
}